// round 6
// baseline (speedup 1.0000x reference)
#include <cuda_runtime.h>

// Problem constants
#define NN   64
#define CC   64
#define TP   300
#define VV   25
#define OO   64
#define NA   3
#define TT   10            // t-rows per block tile
#define TWC  250           // TT*VV columns per tile
#define XSTR 260           // padded smem row stride (mult of 4, not mult of 32)
#define ASTR 28            // padded A row (mult of 4)
#define APITCH (VV*ASTR)   // 700
#define NTOT (64*300*25)   // elements per channel for BN stats
#define NTHR 512

typedef unsigned long long u64;

// ---- packed f32x2 helpers (ptxas never emits FFMA2 from C++) ----
__device__ __forceinline__ u64 pack2(float lo, float hi) {
    u64 r; asm("mov.b64 %0, {%1, %2};" : "=l"(r) : "f"(lo), "f"(hi)); return r;
}
__device__ __forceinline__ void unpack2(u64 v, float& lo, float& hi) {
    asm("mov.b64 {%0, %1}, %2;" : "=f"(lo), "=f"(hi) : "l"(v));
}
__device__ __forceinline__ void fma2(u64& d, u64 a, u64 b) {
    asm("fma.rn.f32x2 %0, %1, %2, %0;" : "+l"(d) : "l"(a), "l"(b));
}

// Scratch (static device allocations are the sanctioned workaround)
__device__ float g_y[(size_t)NN*OO*TP*VV];   // pre-BN activations, 122.88 MB
__device__ float g_sum[OO];
__device__ float g_sumsq[OO];
__device__ float g_scale[OO];
__device__ float g_shift[OO];

__global__ void zero_stats_kernel() {
    g_sum[threadIdx.x]   = 0.f;
    g_sumsq[threadIdx.x] = 0.f;
}

__global__ __launch_bounds__(NTHR, 1) void compute_kernel(
    const float* __restrict__ x,
    const float* __restrict__ A,
    const float* __restrict__ W)
{
    extern __shared__ float smem[];
    float* As = smem;                    // NA*APITCH = 2100 floats (zero-padded rows)
    float* Wt = As + NA*APITCH;          // 12288 floats, [a][c][o]
    float* xs = Wt + NA*4096;            // CC*XSTR
    float* zs = xs + CC*XSTR;            // CC*XSTR

    const int tid = threadIdx.x;
    const int tb  = blockIdx.x;          // 0..29 (t tile)
    const int n   = blockIdx.y;          // 0..63

    // Load A with row padding (pad cols 25..27 = 0)
    for (int i = tid; i < NA*APITCH; i += NTHR) {
        int a = i / APITCH; int r = i - a*APITCH;
        int v = r / ASTR;   int w = r - v*ASTR;
        As[i] = (w < VV) ? A[(a*VV + v)*VV + w] : 0.f;
    }
    // Load W transposed: Wt[a][c][o] = W[a][o][c]
    for (int i = tid; i < NA*4096; i += NTHR) {
        int a = i >> 12; int r = i & 4095;
        int c = r >> 6;  int o = r & 63;
        Wt[i] = W[a*4096 + o*64 + c];
    }
    // Load x tile (float2: both gmem offset and smem stride are 8B-aligned)
    {
        const float* xsrc = x + (size_t)(n*CC)*7500 + (size_t)tb*TWC;
        for (int i = tid; i < CC*(TWC/2); i += NTHR) {
            int c = i / (TWC/2); int r = i - c*(TWC/2);
            *(float2*)(xs + c*XSTR + 2*r) =
                *(const float2*)(xsrc + (size_t)c*7500 + 2*r);
        }
    }
    // Zero zs tail columns [250, 260) (stage-2 reads touch up to 255; products
    // are exactly 0 so stats need no guard)
    for (int i = tid; i < CC*(XSTR-TWC); i += NTHR) {
        int c = i / (XSTR-TWC); int r = i - c*(XSTR-TWC);
        zs[c*XSTR + TWC + r] = 0.f;
    }
    __syncthreads();

    const int wid  = tid >> 5;           // 0..15
    const int lane = tid & 31;
    const int og   = wid << 2;           // warp owns o in [og, og+4)
    const int twb  = lane << 3;          // thread owns tw in [twb, twb+8)

    // acc2[op][tp]: f32x2 pairs over adjacent tw (tw = twb+2*tp {+1}), o = og+op
    u64 acc2[4][4];
    #pragma unroll
    for (int i = 0; i < 4; i++)
        #pragma unroll
        for (int j = 0; j < 4; j++) acc2[i][j] = 0ull;

    for (int a = 0; a < NA; a++) {
        // ---- stage 1: zs[c][t*25+w] = sum_v xs[c][t*25+v] * A[a][v][w] ----
        for (int p = tid; p < CC*TT; p += NTHR) {
            int c = p / TT; int t = p - c*TT;
            const float* xrow = xs + c*XSTR + t*VV;
            u64 zacc[14];
            #pragma unroll
            for (int k = 0; k < 14; k++) zacc[k] = 0ull;
            #pragma unroll 5
            for (int v = 0; v < VV; v++) {
                float xv = xrow[v];
                u64 xv2 = pack2(xv, xv);
                const ulonglong2* a2 = (const ulonglong2*)(As + a*APITCH + v*ASTR);
                #pragma unroll
                for (int k = 0; k < 7; k++) {
                    ulonglong2 av = a2[k];
                    fma2(zacc[2*k],   xv2, av.x);
                    fma2(zacc[2*k+1], xv2, av.y);
                }
            }
            float* zrow = zs + c*XSTR + t*VV;
            float zf[28];
            #pragma unroll
            for (int k = 0; k < 14; k++) unpack2(zacc[k], zf[2*k], zf[2*k+1]);
            #pragma unroll
            for (int w = 0; w < VV; w++) zrow[w] = zf[w];
        }
        __syncthreads();

        // ---- stage 2: acc[o][tw] += W[a,o,c] * zs[c][tw] ----
        // z pairs come directly from LDS.128 as u64 (tw-adjacent); only W
        // needs dup-packing (4 movs per c). 16 fma2 per c per thread.
        const float* wbase = Wt + a*4096 + og;
        #pragma unroll 4
        for (int c = 0; c < CC; c++) {
            float4 wv = *(const float4*)(wbase + c*64);     // broadcast, conflict-free
            u64 wd[4];
            wd[0] = pack2(wv.x, wv.x); wd[1] = pack2(wv.y, wv.y);
            wd[2] = pack2(wv.z, wv.z); wd[3] = pack2(wv.w, wv.w);
            const ulonglong2* zp = (const ulonglong2*)(zs + c*XSTR + twb);
            ulonglong2 za = zp[0], zb = zp[1];
            u64 zd[4] = {za.x, za.y, zb.x, zb.y};
            #pragma unroll
            for (int op = 0; op < 4; op++)
                #pragma unroll
                for (int tp = 0; tp < 4; tp++)
                    fma2(acc2[op][tp], wd[op], zd[tp]);
        }
        __syncthreads();
    }

    // ---- epilogue: store pre-BN y (vectorized), accumulate stats ----
    // Warp wid exclusively owns channels [og, og+4). Tail tw>=250 are exact
    // zeros -> stats unguarded; stores guarded on lane 31.
    float* ybase = g_y + (size_t)(n*OO)*7500 + (size_t)tb*TWC;
    #pragma unroll
    for (int op = 0; op < 4; op++) {
        int o = og + op;
        float yv[8];
        #pragma unroll
        for (int tp = 0; tp < 4; tp++) unpack2(acc2[op][tp], yv[2*tp], yv[2*tp+1]);

        float s = 0.f, sq = 0.f;
        #pragma unroll
        for (int k = 0; k < 8; k++) { s += yv[k]; sq += yv[k]*yv[k]; }

        float* dst = ybase + (size_t)o*7500 + twb;
        if (lane < 31) {
            *(float2*)(dst)     = make_float2(yv[0], yv[1]);
            *(float2*)(dst + 2) = make_float2(yv[2], yv[3]);
            *(float2*)(dst + 4) = make_float2(yv[4], yv[5]);
            *(float2*)(dst + 6) = make_float2(yv[6], yv[7]);
        } else {
            // lane 31 owns tw 248..255 but only 248,249 are in-tile
            *(float2*)(dst)     = make_float2(yv[0], yv[1]);
        }

        #pragma unroll
        for (int off = 16; off; off >>= 1) {
            s  += __shfl_xor_sync(0xFFFFFFFFu, s,  off);
            sq += __shfl_xor_sync(0xFFFFFFFFu, sq, off);
        }
        if (lane == 0) {
            atomicAdd(&g_sum[o],   s);
            atomicAdd(&g_sumsq[o], sq);
        }
    }
}

__global__ void finalize_stats_kernel(const float* __restrict__ gamma,
                                      const float* __restrict__ beta)
{
    int o = threadIdx.x;
    float inv_n = 1.0f / (float)NTOT;
    float mean = g_sum[o] * inv_n;
    float var  = g_sumsq[o] * inv_n - mean * mean;
    float sc   = gamma[o] * rsqrtf(var + 1e-5f);
    g_scale[o] = sc;
    g_shift[o] = beta[o] - mean * sc;
}

__global__ __launch_bounds__(256) void apply_kernel(float* __restrict__ out)
{
    int no = blockIdx.x;                 // n*64 + o
    int o  = no & 63;
    float sc = g_scale[o];
    float sh = g_shift[o];
    const float4* src = (const float4*)(g_y + (size_t)no*7500);
    float4*       dst = (float4*)(out + (size_t)no*7500);
    for (int i = threadIdx.x; i < 7500/4; i += 256) {
        float4 v = src[i];
        v.x = fmaxf(fmaf(v.x, sc, sh), 0.f);
        v.y = fmaxf(fmaf(v.y, sc, sh), 0.f);
        v.z = fmaxf(fmaf(v.z, sc, sh), 0.f);
        v.w = fmaxf(fmaf(v.w, sc, sh), 0.f);
        dst[i] = v;
    }
}

extern "C" void kernel_launch(void* const* d_in, const int* in_sizes, int n_in,
                              void* d_out, int out_size)
{
    const float* x     = (const float*)d_in[0];
    const float* A     = (const float*)d_in[1];
    const float* W     = (const float*)d_in[2];
    // d_in[3] = b: cancelled exactly by training-mode BatchNorm mean subtraction
    const float* gamma = (const float*)d_in[4];
    const float* beta  = (const float*)d_in[5];
    float* out = (float*)d_out;

    const size_t smem_bytes =
        (size_t)(NA*APITCH + NA*4096 + 2*CC*XSTR) * sizeof(float); // ~190.7 KB
    cudaFuncSetAttribute(compute_kernel,
                         cudaFuncAttributeMaxDynamicSharedMemorySize,
                         (int)smem_bytes);

    zero_stats_kernel<<<1, OO>>>();
    compute_kernel<<<dim3(TP/TT, NN), NTHR, smem_bytes>>>(x, A, W);
    finalize_stats_kernel<<<1, OO>>>(gamma, beta);
    apply_kernel<<<NN*OO, 256>>>(out);
}